// round 12
// baseline (speedup 1.0000x reference)
#include <cuda_runtime.h>

#define Bn 2048
#define NB 2000
#define DB 30
#define KK 20
#define LL 40
#define PP 2
#define KSPLIT 8
#define KCH 250         // NB / KSPLIT

typedef unsigned long long u64;

#define LOG2E 1.44269504088896f
#define LN2   0.69314718055995f

// Blob layout (u64 units) per (k,l)
#define OFF_L1 0        // 64:  [p][i] (w*log2e dup, b*log2e dup) as ulonglong2
#define OFF_W2 64       // 512: [p][i][j] dup(W2*log2e)
#define OFF_B2 576      // 32:  [p][i]   dup((b2 - rowsum W2)*log2e)
#define OFF_W3 608      // 256: [p][j][q] dup(W3*log2e)
#define OFF_B3 864      // 16:  [p][j]   dup((b3 - rowsum W3)*log2e)
#define OFF_W4 880      // 16:  [p][j]   dup(W4)
#define OFF_B4 896      // 2:   [p]      dup(b4 - sum W4)
#define OFF_AA 898      // 1:   dup(sigmoid(alpha))
#define BLOBU  904      // padded, 16B-aligned total (7232 B)

// Scratch (no allocations allowed in kernel_launch)
__device__ float d_wact[NB * LL];               // sigmoid(r - kappa)   [NB, L]
__device__ float d_gpart[KSPLIT * LL * Bn];     // split-K partials     [ks, L, B]
__device__ float d_g[LL * Bn];                  // reduced g            [L, B]
__device__ float d_partial[LL * KK * Bn];       // per-(l,k) outputs    [L, K, B]
__device__ __align__(16) u64 d_blob[800 * BLOBU];  // preprocessed weights

// ---------------- packed f32x2 helpers --------------------------------------
__device__ __forceinline__ u64 pack2(float lo, float hi) {
    u64 r; asm("mov.b64 %0, {%1, %2};" : "=l"(r) : "f"(lo), "f"(hi)); return r;
}
__device__ __forceinline__ void unpack2(u64 v, float& lo, float& hi) {
    asm("mov.b64 {%0, %1}, %2;" : "=f"(lo), "=f"(hi) : "l"(v));
}
__device__ __forceinline__ u64 ffma2(u64 a, u64 b, u64 c) {
    u64 d; asm("fma.rn.f32x2 %0, %1, %2, %3;" : "=l"(d) : "l"(a), "l"(b), "l"(c)); return d;
}
__device__ __forceinline__ u64 fadd2(u64 a, u64 b) {
    u64 d; asm("add.rn.f32x2 %0, %1, %2;" : "=l"(d) : "l"(a), "l"(b)); return d;
}
__device__ __forceinline__ u64 fmul2(u64 a, u64 b) {
    u64 d; asm("mul.rn.f32x2 %0, %1, %2;" : "=l"(d) : "l"(a), "l"(b)); return d;
}
__device__ __forceinline__ float ex2(float x) {
    float r; asm("ex2.approx.f32 %0, %1;" : "=f"(r) : "f"(x)); return r;
}

// ELU variant M (MUFU). Input z' pre-scaled by log2e.
// elu(z)+1 = ln2*max(z',0) + exp2(min(z',0)).
__device__ __forceinline__ float elup1s(float zp) {
    return fmaf(fmaxf(zp, 0.f), LN2, ex2(fminf(zp, 0.f)));
}
__device__ __forceinline__ u64 elup1s_2(u64 z) {
    float lo, hi; unpack2(z, lo, hi);
    return pack2(elup1s(lo), elup1s(hi));
}

// ELU variant P (fma/alu-pipe scalar polynomial exp2; ALL constants are
// instruction immediates -> zero persistent registers, FFMA-imm rt 1).
__device__ __forceinline__ float elup1p(float zp) {
    float mn = fmaxf(fminf(zp, 0.f), -126.f);
    float mx = fmaxf(zp, 0.f);
    float t  = mn + 12582912.f;            // round-to-int magic (1.5*2^23)
    float n  = t - 12582912.f;
    float f  = mn - n;                     // f in [-0.5, 0.5]
    float p  = fmaf(1.3333558e-3f, f, 9.6181291e-3f);
    p = fmaf(p, f, 5.5504109e-2f);
    p = fmaf(p, f, 2.4022651e-1f);
    p = fmaf(p, f, 6.9314718e-1f);
    p = fmaf(p, f, 1.f);
    int i = __float_as_int(t) * 8388608 + 0x3F800000;   // bits of 2^n
    float e = p * __int_as_float(i);
    return fmaf(mx, LN2, e);
}
__device__ __forceinline__ u64 elup1p_2(u64 z) {
    float lo, hi; unpack2(z, lo, hi);
    return pack2(elup1p(lo), elup1p(hi));
}

// ---------------------------------------------------------------------------
// Kernel A: w_act[m,l] = sigmoid(r[l] - ||ml[m]-mu[l]||^2), smem-staged.
// ---------------------------------------------------------------------------
#define MT 32
#define DPAD 32

__global__ __launch_bounds__(256) void k_wact(const float* __restrict__ ml,
                                              const float* __restrict__ mu,
                                              const float* __restrict__ r) {
    __shared__ __align__(16) float s_mu[LL * DPAD];
    __shared__ __align__(16) float s_ml[MT * DPAD];
    __shared__ float s_r[LL];
    int tid = threadIdx.x;
    int m0  = blockIdx.x * MT;

    for (int e = tid; e < LL * DB; e += 256) {
        int l = e / DB, d = e % DB;
        s_mu[l * DPAD + d] = mu[e];
    }
    for (int e = tid; e < MT * DB; e += 256) {
        int mm = e / DB, d = e % DB;
        int m = m0 + mm;
        s_ml[mm * DPAD + d] = (m < NB) ? ml[m * DB + d] : 0.f;
    }
    if (tid < LL) s_r[tid] = r[tid];
    __syncthreads();

    int mm = tid & 31;
    int lg = tid >> 5;
    int m  = m0 + mm;
    if (m >= NB) return;

    float a[DB];
#pragma unroll
    for (int d = 0; d < DB; d++) a[d] = s_ml[mm * DPAD + d];

#pragma unroll
    for (int li = 0; li < 5; li++) {
        int l = lg * 5 + li;
        const float* c = &s_mu[l * DPAD];
        float s = 0.f;
#pragma unroll
        for (int d = 0; d < DB; d++) { float t = a[d] - c[d]; s = fmaf(t, t, s); }
        float z = s_r[l] - s;
        d_wact[m * LL + l] = 1.0f / (1.0f + __expf(-z));
    }
}

// ---------------------------------------------------------------------------
// Kernel P: preprocess weights into per-(k,l) gmem blobs (smem image).
// ---------------------------------------------------------------------------
__global__ __launch_bounds__(128) void k_prep(
    const float* __restrict__ W1, const float* __restrict__ b1,
    const float* __restrict__ W2, const float* __restrict__ b2,
    const float* __restrict__ W3, const float* __restrict__ b3,
    const float* __restrict__ W4, const float* __restrict__ b4,
    const float* __restrict__ alpha) {
    int kl = blockIdx.x;
    int k = kl / LL, l = kl % LL;
    int tid  = threadIdx.x;
    int base = kl * PP;
    u64* blob = d_blob + (size_t)kl * BLOBU;

    if (tid < 32) {
        int p = tid >> 4, i = tid & 15;
        float w = W1[base * 16 + tid] * LOG2E;
        float a = b1[base * 16 + tid] * LOG2E;
        blob[OFF_L1 + (p * 16 + i) * 2]     = pack2(w, w);
        blob[OFF_L1 + (p * 16 + i) * 2 + 1] = pack2(a, a);
        float c = b2[base * 16 + tid];
        const float* w2p = W2 + base * 256 + p * 256;
#pragma unroll
        for (int ii = 0; ii < 16; ii++) c -= w2p[ii * 16 + i];
        c *= LOG2E;
        blob[OFF_B2 + p * 16 + i] = pack2(c, c);
    }
#pragma unroll
    for (int e = tid; e < PP * 256; e += 128) {
        float w = W2[base * 256 + e] * LOG2E;
        blob[OFF_W2 + e] = pack2(w, w);
    }
#pragma unroll
    for (int e = tid; e < PP * 128; e += 128) {
        float w = W3[base * 128 + e] * LOG2E;
        blob[OFF_W3 + e] = pack2(w, w);
    }
    if (tid < 16) {
        int p = tid >> 3, j = tid & 7;
        float a = b3[base * 8 + tid];
        const float* w3p = W3 + base * 128 + p * 128;
#pragma unroll
        for (int ii = 0; ii < 16; ii++) a -= w3p[ii * 8 + j];
        a *= LOG2E;
        blob[OFF_B3 + tid] = pack2(a, a);
        float w = W4[base * 8 + tid];
        blob[OFF_W4 + tid] = pack2(w, w);
    }
    if (tid < 2) {
        float a = b4[base + tid];
        const float* w4p = W4 + base * 8 + tid * 8;
#pragma unroll
        for (int ii = 0; ii < 8; ii++) a -= w4p[ii];
        blob[OFF_B4 + tid] = pack2(a, a);
    }
    if (tid == 0) {
        float aAct = 1.0f / (1.0f + __expf(-alpha[l * KK + k]));
        blob[OFF_AA] = pack2(aAct, aAct);
    }
}

// ---------------------------------------------------------------------------
// Kernel B: split-K GEMM (KSPLIT=8). gpart[ks,l,b] = sum_slice x[b,m]*wact[m,l]
// ---------------------------------------------------------------------------
#define CH 128
#define XS 132
#define WS 132

__global__ __launch_bounds__(320) void k_gemm(const float* __restrict__ x) {
    __shared__ __align__(16) float xs[16 * XS];
    __shared__ __align__(16) float ws[LL * WS];     // [l][mm]
    int b0   = blockIdx.x * 16;
    int ks   = blockIdx.y;
    int mlo  = ks * KCH;
    int mend = mlo + KCH;
    int tid = threadIdx.x;
    int row = tid & 15;
    int cg  = tid >> 4;
    u64 acc0 = 0ull, acc1 = 0ull;
    for (int m0 = mlo; m0 < mend; m0 += CH) {
        for (int e = tid; e < 16 * CH; e += 320) {
            int rr = e >> 7, cc = e & (CH - 1);
            int m = m0 + cc;
            xs[rr * XS + cc] = (m < mend) ? x[(b0 + rr) * NB + m] : 0.f;
        }
        for (int e = tid; e < CH * LL; e += 320) {
            int mm = e / LL, l = e % LL;
            int m = m0 + mm;
            ws[l * WS + mm] = (m < mend) ? d_wact[m * LL + l] : 0.f;
        }
        __syncthreads();
#pragma unroll 4
        for (int mm = 0; mm < CH; mm += 4) {
            float4 xv = *(const float4*)&xs[row * XS + mm];
            float4 w0 = *(const float4*)&ws[(2 * cg)     * WS + mm];
            float4 w1 = *(const float4*)&ws[(2 * cg + 1) * WS + mm];
            u64 xa = pack2(xv.x, xv.y), xb = pack2(xv.z, xv.w);
            acc0 = ffma2(xa, pack2(w0.x, w0.y), acc0);
            acc0 = ffma2(xb, pack2(w0.z, w0.w), acc0);
            acc1 = ffma2(xa, pack2(w1.x, w1.y), acc1);
            acc1 = ffma2(xb, pack2(w1.z, w1.w), acc1);
        }
        __syncthreads();
    }
    float a0l, a0h, a1l, a1h;
    unpack2(acc0, a0l, a0h);
    unpack2(acc1, a1l, a1h);
    float* gp = d_gpart + ks * (LL * Bn);
    gp[(2 * cg)     * Bn + b0 + row] = a0l + a0h;
    gp[(2 * cg + 1) * Bn + b0 + row] = a1l + a1h;
}

// ---------------------------------------------------------------------------
// Kernel S: d_g = sum over KSPLIT slices of d_gpart
// ---------------------------------------------------------------------------
__global__ __launch_bounds__(256) void k_sum() {
    int idx = blockIdx.x * blockDim.x + threadIdx.x;
    if (idx >= LL * Bn) return;
    float s = 0.f;
#pragma unroll
    for (int ks = 0; ks < KSPLIT; ks++) s += d_gpart[ks * (LL * Bn) + idx];
    d_g[idx] = s;
}

// ---------------------------------------------------------------------------
// Kernel C: NAM. 6400 light blocks, 64 threads, 8 blocks/SM. Hybrid ELU:
// pair A = MUFU ex2 path, pair B = scalar immediate-constant polynomial
// (fma/alu pipes) -> MUFU density 10% -> 3.7%, well under rt-8 saturation.
// ---------------------------------------------------------------------------
__global__ __launch_bounds__(64, 8) void k_nam() {
    __shared__ __align__(16) u64 sm[BLOBU];
    int unit = blockIdx.x;
    int kl = unit >> 3, e8 = unit & 7;
    int tid = threadIdx.x;

    const u64* blob = d_blob + (size_t)kl * BLOBU;
#pragma unroll
    for (int e = tid; e < BLOBU / 2; e += 64)
        ((ulonglong2*)sm)[e] = ((const ulonglong2*)blob)[e];
    __syncthreads();

    int k = kl / LL, l = kl % LL;
    u64 aAct2 = sm[OFF_AA];
    float* outp = d_partial + (l * KK + k) * Bn + e8 * 256;
    const float* gp = d_g + l * Bn + e8 * 256;

    int b0 = 2 * tid;                       // pairA at b0, pairB at b0+128
    float2 g0 = *(const float2*)&gp[b0];
    float2 g1 = *(const float2*)&gp[b0 + 128];
    u64 GA = pack2(g0.x, g0.y);
    u64 GB = pack2(g1.x, g1.y);
    u64 SA = 0ull, SB = 0ull;

#pragma unroll 1
    for (int p = 0; p < PP; p++) {
        // ---- layer 1 streamed into layer-2 accumulators ----
        u64 a2[16][2];
#pragma unroll
        for (int j = 0; j < 16; j++) {
            u64 bb = sm[OFF_B2 + p * 16 + j];
            a2[j][0] = bb; a2[j][1] = bb;
        }
#pragma unroll
        for (int i = 0; i < 16; i++) {
            ulonglong2 wb = ((const ulonglong2*)(sm + OFF_L1))[p * 16 + i];
            u64 hA = elup1s_2(ffma2(GA, wb.x, wb.y));
            u64 hB = elup1p_2(ffma2(GB, wb.x, wb.y));
            const ulonglong2* wr = (const ulonglong2*)(sm + OFF_W2 + p * 256 + i * 16);
#pragma unroll
            for (int q = 0; q < 8; q++) {
                ulonglong2 w = wr[q];
                a2[2 * q][0]     = ffma2(hA, w.x, a2[2 * q][0]);
                a2[2 * q + 1][0] = ffma2(hA, w.y, a2[2 * q + 1][0]);
                a2[2 * q][1]     = ffma2(hB, w.x, a2[2 * q][1]);
                a2[2 * q + 1][1] = ffma2(hB, w.y, a2[2 * q + 1][1]);
            }
        }

        // ---- layer 2 -> layer 3 accumulators ----
        u64 a3[8][2];
#pragma unroll
        for (int q = 0; q < 8; q++) {
            u64 bb = sm[OFF_B3 + p * 8 + q];
            a3[q][0] = bb; a3[q][1] = bb;
        }
#pragma unroll
        for (int j = 0; j < 16; j++) {
            u64 vA = elup1s_2(a2[j][0]);
            u64 vB = elup1p_2(a2[j][1]);
            const ulonglong2* wr = (const ulonglong2*)(sm + OFF_W3 + p * 128 + j * 8);
#pragma unroll
            for (int q = 0; q < 4; q++) {
                ulonglong2 w = wr[q];
                a3[2 * q][0]     = ffma2(vA, w.x, a3[2 * q][0]);
                a3[2 * q + 1][0] = ffma2(vA, w.y, a3[2 * q + 1][0]);
                a3[2 * q][1]     = ffma2(vB, w.x, a3[2 * q][1]);
                a3[2 * q + 1][1] = ffma2(vB, w.y, a3[2 * q + 1][1]);
            }
        }

        // ---- layer 3 -> scalar ----
        u64 fA = sm[OFF_B4 + p], fB = fA;
#pragma unroll
        for (int j = 0; j < 8; j++) {
            u64 vA = elup1s_2(a3[j][0]);
            u64 vB = elup1p_2(a3[j][1]);
            u64 w = sm[OFF_W4 + p * 8 + j];
            fA = ffma2(vA, w, fA);
            fB = ffma2(vB, w, fB);
        }
        SA = fadd2(SA, fA);
        SB = fadd2(SB, fB);
    }

    u64 r0 = fmul2(aAct2, SA);
    u64 r1 = fmul2(aAct2, SB);
    float lo, hi;
    unpack2(r0, lo, hi); *(float2*)&outp[b0]       = make_float2(lo, hi);
    unpack2(r1, lo, hi); *(float2*)&outp[b0 + 128] = make_float2(lo, hi);
}

// ---------------------------------------------------------------------------
// Kernel D: out[b,k] = beta[k] + sum_l partial[l,k,b]  (scalar, high-occ)
// ---------------------------------------------------------------------------
__global__ void k_out(const float* __restrict__ beta, float* __restrict__ out) {
    int idx = blockIdx.x * blockDim.x + threadIdx.x;
    if (idx >= KK * Bn) return;
    int k = idx >> 11;
    int b = idx & (Bn - 1);
    float s = beta[k];
#pragma unroll
    for (int l = 0; l < LL; l++) s += d_partial[(l * KK + k) * Bn + b];
    out[b * KK + k] = s;
}

// ---------------------------------------------------------------------------
extern "C" void kernel_launch(void* const* d_in, const int* in_sizes, int n_in,
                              void* d_out, int out_size) {
    const float* x     = (const float*)d_in[0];
    const float* ml    = (const float*)d_in[1];
    const float* mu    = (const float*)d_in[2];
    const float* r     = (const float*)d_in[3];
    const float* alpha = (const float*)d_in[4];
    const float* beta  = (const float*)d_in[5];
    const float* W1    = (const float*)d_in[6];
    const float* b1    = (const float*)d_in[7];
    const float* W2    = (const float*)d_in[8];
    const float* b2    = (const float*)d_in[9];
    const float* W3    = (const float*)d_in[10];
    const float* b3    = (const float*)d_in[11];
    const float* W4    = (const float*)d_in[12];
    const float* b4    = (const float*)d_in[13];
    float* out = (float*)d_out;

    k_wact<<<(NB + MT - 1) / MT, 256>>>(ml, mu, r);
    k_prep<<<KK * LL, 128>>>(W1, b1, W2, b2, W3, b3, W4, b4, alpha);
    dim3 ggrid(Bn / 16, KSPLIT);
    k_gemm<<<ggrid, 320>>>(x);
    k_sum<<<(LL * Bn + 255) / 256, 256>>>();
    k_nam<<<KK * LL * 8, 64>>>();
    k_out<<<(KK * Bn + 255) / 256, 256>>>(beta, out);
}

// round 14
// speedup vs baseline: 1.1342x; 1.1342x over previous
#include <cuda_runtime.h>

#define Bn 2048
#define NB 2000
#define DB 30
#define KK 20
#define LL 40
#define PP 2
#define KSPLIT 8
#define KCH 250         // NB / KSPLIT

typedef unsigned long long u64;

#define LOG2E 1.44269504088896f
#define LN2   0.69314718055995f

// Blob layout (u64 units) per (k,l)
#define OFF_L1 0        // 64:  [p][i] (w*log2e dup, b*log2e dup) as ulonglong2
#define OFF_W2 64       // 512: [p][i][j] dup(W2*log2e)
#define OFF_B2 576      // 32:  [p][i]   dup((b2 - rowsum W2)*log2e)
#define OFF_W3 608      // 256: [p][j][q] dup(W3*log2e)
#define OFF_B3 864      // 16:  [p][j]   dup((b3 - rowsum W3)*log2e)
#define OFF_W4 880      // 16:  [p][j]   dup(W4)
#define OFF_B4 896      // 2:   [p]      dup(b4 - sum W4)
#define OFF_AA 898      // 1:   dup(sigmoid(alpha))
#define BLOBU  904      // padded, 16B-aligned total (7232 B)

// Scratch (no allocations allowed in kernel_launch)
__device__ float d_wact[NB * LL];               // sigmoid(r - kappa)   [NB, L]
__device__ float d_gpart[KSPLIT * LL * Bn];     // split-K partials     [ks, L, B]
__device__ float d_partial[LL * KK * Bn];       // per-(l,k) outputs    [L, K, B]
__device__ __align__(16) u64 d_blob[800 * BLOBU];  // preprocessed weights

// ---------------- packed f32x2 helpers --------------------------------------
__device__ __forceinline__ u64 pack2(float lo, float hi) {
    u64 r; asm("mov.b64 %0, {%1, %2};" : "=l"(r) : "f"(lo), "f"(hi)); return r;
}
__device__ __forceinline__ void unpack2(u64 v, float& lo, float& hi) {
    asm("mov.b64 {%0, %1}, %2;" : "=f"(lo), "=f"(hi) : "l"(v));
}
__device__ __forceinline__ u64 ffma2(u64 a, u64 b, u64 c) {
    u64 d; asm("fma.rn.f32x2 %0, %1, %2, %3;" : "=l"(d) : "l"(a), "l"(b), "l"(c)); return d;
}
__device__ __forceinline__ u64 fadd2(u64 a, u64 b) {
    u64 d; asm("add.rn.f32x2 %0, %1, %2;" : "=l"(d) : "l"(a), "l"(b)); return d;
}
__device__ __forceinline__ u64 fmul2(u64 a, u64 b) {
    u64 d; asm("mul.rn.f32x2 %0, %1, %2;" : "=l"(d) : "l"(a), "l"(b)); return d;
}
__device__ __forceinline__ float ex2(float x) {
    float r; asm("ex2.approx.f32 %0, %1;" : "=f"(r) : "f"(x)); return r;
}
// ELU (clamp form, CORRECT on both branches). Input z' = z*log2e.
// elu(z)+1 = ln2*max(z',0) + exp2(min(z',0)).
__device__ __forceinline__ float elup1s(float zp) {
    return fmaf(fmaxf(zp, 0.f), LN2, ex2(fminf(zp, 0.f)));
}
__device__ __forceinline__ u64 elup1s_2(u64 z) {
    float lo, hi; unpack2(z, lo, hi);
    return pack2(elup1s(lo), elup1s(hi));
}

// ---------------------------------------------------------------------------
// Kernel A: w_act[m,l] = sigmoid(r[l] - ||ml[m]-mu[l]||^2), smem-staged.
// ---------------------------------------------------------------------------
#define MT 32
#define DPAD 32

__global__ __launch_bounds__(256) void k_wact(const float* __restrict__ ml,
                                              const float* __restrict__ mu,
                                              const float* __restrict__ r) {
    __shared__ __align__(16) float s_mu[LL * DPAD];
    __shared__ __align__(16) float s_ml[MT * DPAD];
    __shared__ float s_r[LL];
    int tid = threadIdx.x;
    int m0  = blockIdx.x * MT;

    for (int e = tid; e < LL * DB; e += 256) {
        int l = e / DB, d = e % DB;
        s_mu[l * DPAD + d] = mu[e];
    }
    for (int e = tid; e < MT * DB; e += 256) {
        int mm = e / DB, d = e % DB;
        int m = m0 + mm;
        s_ml[mm * DPAD + d] = (m < NB) ? ml[m * DB + d] : 0.f;
    }
    if (tid < LL) s_r[tid] = r[tid];
    __syncthreads();

    int mm = tid & 31;
    int lg = tid >> 5;
    int m  = m0 + mm;
    if (m >= NB) return;

    float a[DB];
#pragma unroll
    for (int d = 0; d < DB; d++) a[d] = s_ml[mm * DPAD + d];

#pragma unroll
    for (int li = 0; li < 5; li++) {
        int l = lg * 5 + li;
        const float* c = &s_mu[l * DPAD];
        float s = 0.f;
#pragma unroll
        for (int d = 0; d < DB; d++) { float t = a[d] - c[d]; s = fmaf(t, t, s); }
        float z = s_r[l] - s;
        d_wact[m * LL + l] = 1.0f / (1.0f + __expf(-z));
    }
}

// ---------------------------------------------------------------------------
// Kernel P: preprocess weights into per-(k,l) gmem blobs (smem image).
// ---------------------------------------------------------------------------
__global__ __launch_bounds__(128) void k_prep(
    const float* __restrict__ W1, const float* __restrict__ b1,
    const float* __restrict__ W2, const float* __restrict__ b2,
    const float* __restrict__ W3, const float* __restrict__ b3,
    const float* __restrict__ W4, const float* __restrict__ b4,
    const float* __restrict__ alpha) {
    int kl = blockIdx.x;
    int k = kl / LL, l = kl % LL;
    int tid  = threadIdx.x;
    int base = kl * PP;
    u64* blob = d_blob + (size_t)kl * BLOBU;

    if (tid < 32) {
        int p = tid >> 4, i = tid & 15;
        float w = W1[base * 16 + tid] * LOG2E;
        float a = b1[base * 16 + tid] * LOG2E;
        blob[OFF_L1 + (p * 16 + i) * 2]     = pack2(w, w);
        blob[OFF_L1 + (p * 16 + i) * 2 + 1] = pack2(a, a);
        float c = b2[base * 16 + tid];
        const float* w2p = W2 + base * 256 + p * 256;
#pragma unroll
        for (int ii = 0; ii < 16; ii++) c -= w2p[ii * 16 + i];
        c *= LOG2E;
        blob[OFF_B2 + p * 16 + i] = pack2(c, c);
    }
#pragma unroll
    for (int e = tid; e < PP * 256; e += 128) {
        float w = W2[base * 256 + e] * LOG2E;
        blob[OFF_W2 + e] = pack2(w, w);
    }
#pragma unroll
    for (int e = tid; e < PP * 128; e += 128) {
        float w = W3[base * 128 + e] * LOG2E;
        blob[OFF_W3 + e] = pack2(w, w);
    }
    if (tid < 16) {
        int p = tid >> 3, j = tid & 7;
        float a = b3[base * 8 + tid];
        const float* w3p = W3 + base * 128 + p * 128;
#pragma unroll
        for (int ii = 0; ii < 16; ii++) a -= w3p[ii * 8 + j];
        a *= LOG2E;
        blob[OFF_B3 + tid] = pack2(a, a);
        float w = W4[base * 8 + tid];
        blob[OFF_W4 + tid] = pack2(w, w);
    }
    if (tid < 2) {
        float a = b4[base + tid];
        const float* w4p = W4 + base * 8 + tid * 8;
#pragma unroll
        for (int ii = 0; ii < 8; ii++) a -= w4p[ii];
        blob[OFF_B4 + tid] = pack2(a, a);
    }
    if (tid == 0) {
        float aAct = 1.0f / (1.0f + __expf(-alpha[l * KK + k]));
        blob[OFF_AA] = pack2(aAct, aAct);
    }
}

// ---------------------------------------------------------------------------
// Kernel B: split-K GEMM (KSPLIT=8). gpart[ks,l,b] = sum_slice x[b,m]*wact[m,l]
// ---------------------------------------------------------------------------
#define CH 128
#define XS 132
#define WS 132

__global__ __launch_bounds__(320) void k_gemm(const float* __restrict__ x) {
    __shared__ __align__(16) float xs[16 * XS];
    __shared__ __align__(16) float ws[LL * WS];     // [l][mm]
    int b0   = blockIdx.x * 16;
    int ks   = blockIdx.y;
    int mlo  = ks * KCH;
    int mend = mlo + KCH;
    int tid = threadIdx.x;
    int row = tid & 15;
    int cg  = tid >> 4;
    u64 acc0 = 0ull, acc1 = 0ull;
    for (int m0 = mlo; m0 < mend; m0 += CH) {
        for (int e = tid; e < 16 * CH; e += 320) {
            int rr = e >> 7, cc = e & (CH - 1);
            int m = m0 + cc;
            xs[rr * XS + cc] = (m < mend) ? x[(b0 + rr) * NB + m] : 0.f;
        }
        for (int e = tid; e < CH * LL; e += 320) {
            int mm = e / LL, l = e % LL;
            int m = m0 + mm;
            ws[l * WS + mm] = (m < mend) ? d_wact[m * LL + l] : 0.f;
        }
        __syncthreads();
#pragma unroll 4
        for (int mm = 0; mm < CH; mm += 4) {
            float4 xv = *(const float4*)&xs[row * XS + mm];
            float4 w0 = *(const float4*)&ws[(2 * cg)     * WS + mm];
            float4 w1 = *(const float4*)&ws[(2 * cg + 1) * WS + mm];
            u64 xa = pack2(xv.x, xv.y), xb = pack2(xv.z, xv.w);
            acc0 = ffma2(xa, pack2(w0.x, w0.y), acc0);
            acc0 = ffma2(xb, pack2(w0.z, w0.w), acc0);
            acc1 = ffma2(xa, pack2(w1.x, w1.y), acc1);
            acc1 = ffma2(xb, pack2(w1.z, w1.w), acc1);
        }
        __syncthreads();
    }
    float a0l, a0h, a1l, a1h;
    unpack2(acc0, a0l, a0h);
    unpack2(acc1, a1l, a1h);
    float* gp = d_gpart + ks * (LL * Bn);
    gp[(2 * cg)     * Bn + b0 + row] = a0l + a0h;
    gp[(2 * cg + 1) * Bn + b0 + row] = a1l + a1h;
}

// ---------------------------------------------------------------------------
// Kernel C: NAM. 6400 light blocks, 64 threads, 8 blocks/SM. Clamp-form MUFU
// ELU (4 instrs/scalar). g reconstructed from the 8 split-K partials inline.
// ---------------------------------------------------------------------------
__global__ __launch_bounds__(64, 8) void k_nam() {
    __shared__ __align__(16) u64 sm[BLOBU];
    int unit = blockIdx.x;
    int kl = unit >> 3, e8 = unit & 7;
    int tid = threadIdx.x;

    const u64* blob = d_blob + (size_t)kl * BLOBU;
#pragma unroll
    for (int e = tid; e < BLOBU / 2; e += 64)
        ((ulonglong2*)sm)[e] = ((const ulonglong2*)blob)[e];
    __syncthreads();

    int k = kl / LL, l = kl % LL;
    u64 aAct2 = sm[OFF_AA];
    float* outp = d_partial + (l * KK + k) * Bn + e8 * 256;
    const float* gp = d_gpart + l * Bn + e8 * 256;

    int b0 = 2 * tid;                       // pairA at b0, pairB at b0+128
    u64 GA = 0ull, GB = 0ull;
#pragma unroll
    for (int ks = 0; ks < KSPLIT; ks++) {
        float2 va = *(const float2*)&gp[ks * (LL * Bn) + b0];
        float2 vb = *(const float2*)&gp[ks * (LL * Bn) + b0 + 128];
        GA = fadd2(GA, pack2(va.x, va.y));
        GB = fadd2(GB, pack2(vb.x, vb.y));
    }
    u64 SA = 0ull, SB = 0ull;

#pragma unroll 1
    for (int p = 0; p < PP; p++) {
        // ---- layer 1 streamed into layer-2 accumulators ----
        u64 a2[16][2];
#pragma unroll
        for (int j = 0; j < 16; j++) {
            u64 bb = sm[OFF_B2 + p * 16 + j];
            a2[j][0] = bb; a2[j][1] = bb;
        }
#pragma unroll
        for (int i = 0; i < 16; i++) {
            ulonglong2 wb = ((const ulonglong2*)(sm + OFF_L1))[p * 16 + i];
            u64 hA = elup1s_2(ffma2(GA, wb.x, wb.y));
            u64 hB = elup1s_2(ffma2(GB, wb.x, wb.y));
            const ulonglong2* wr = (const ulonglong2*)(sm + OFF_W2 + p * 256 + i * 16);
#pragma unroll
            for (int q = 0; q < 8; q++) {
                ulonglong2 w = wr[q];
                a2[2 * q][0]     = ffma2(hA, w.x, a2[2 * q][0]);
                a2[2 * q + 1][0] = ffma2(hA, w.y, a2[2 * q + 1][0]);
                a2[2 * q][1]     = ffma2(hB, w.x, a2[2 * q][1]);
                a2[2 * q + 1][1] = ffma2(hB, w.y, a2[2 * q + 1][1]);
            }
        }

        // ---- layer 2 -> layer 3 accumulators ----
        u64 a3[8][2];
#pragma unroll
        for (int q = 0; q < 8; q++) {
            u64 bb = sm[OFF_B3 + p * 8 + q];
            a3[q][0] = bb; a3[q][1] = bb;
        }
#pragma unroll
        for (int j = 0; j < 16; j++) {
            u64 vA = elup1s_2(a2[j][0]);
            u64 vB = elup1s_2(a2[j][1]);
            const ulonglong2* wr = (const ulonglong2*)(sm + OFF_W3 + p * 128 + j * 8);
#pragma unroll
            for (int q = 0; q < 4; q++) {
                ulonglong2 w = wr[q];
                a3[2 * q][0]     = ffma2(vA, w.x, a3[2 * q][0]);
                a3[2 * q + 1][0] = ffma2(vA, w.y, a3[2 * q + 1][0]);
                a3[2 * q][1]     = ffma2(vB, w.x, a3[2 * q][1]);
                a3[2 * q + 1][1] = ffma2(vB, w.y, a3[2 * q + 1][1]);
            }
        }

        // ---- layer 3 -> scalar ----
        u64 fA = sm[OFF_B4 + p], fB = fA;
#pragma unroll
        for (int j = 0; j < 8; j++) {
            u64 vA = elup1s_2(a3[j][0]);
            u64 vB = elup1s_2(a3[j][1]);
            u64 w = sm[OFF_W4 + p * 8 + j];
            fA = ffma2(vA, w, fA);
            fB = ffma2(vB, w, fB);
        }
        SA = fadd2(SA, fA);
        SB = fadd2(SB, fB);
    }

    u64 r0 = fmul2(aAct2, SA);
    u64 r1 = fmul2(aAct2, SB);
    float lo, hi;
    unpack2(r0, lo, hi); *(float2*)&outp[b0]       = make_float2(lo, hi);
    unpack2(r1, lo, hi); *(float2*)&outp[b0 + 128] = make_float2(lo, hi);
}

// ---------------------------------------------------------------------------
// Kernel D: out[b,k] = beta[k] + sum_l partial[l,k,b]  (scalar, high-occ)
// ---------------------------------------------------------------------------
__global__ void k_out(const float* __restrict__ beta, float* __restrict__ out) {
    int idx = blockIdx.x * blockDim.x + threadIdx.x;
    if (idx >= KK * Bn) return;
    int k = idx >> 11;
    int b = idx & (Bn - 1);
    float s = beta[k];
#pragma unroll
    for (int l = 0; l < LL; l++) s += d_partial[(l * KK + k) * Bn + b];
    out[b * KK + k] = s;
}

// ---------------------------------------------------------------------------
extern "C" void kernel_launch(void* const* d_in, const int* in_sizes, int n_in,
                              void* d_out, int out_size) {
    const float* x     = (const float*)d_in[0];
    const float* ml    = (const float*)d_in[1];
    const float* mu    = (const float*)d_in[2];
    const float* r     = (const float*)d_in[3];
    const float* alpha = (const float*)d_in[4];
    const float* beta  = (const float*)d_in[5];
    const float* W1    = (const float*)d_in[6];
    const float* b1    = (const float*)d_in[7];
    const float* W2    = (const float*)d_in[8];
    const float* b2    = (const float*)d_in[9];
    const float* W3    = (const float*)d_in[10];
    const float* b3    = (const float*)d_in[11];
    const float* W4    = (const float*)d_in[12];
    const float* b4    = (const float*)d_in[13];
    float* out = (float*)d_out;

    k_wact<<<(NB + MT - 1) / MT, 256>>>(ml, mu, r);
    k_prep<<<KK * LL, 128>>>(W1, b1, W2, b2, W3, b3, W4, b4, alpha);
    dim3 ggrid(Bn / 16, KSPLIT);
    k_gemm<<<ggrid, 320>>>(x);
    k_nam<<<KK * LL * 8, 64>>>();
    k_out<<<(KK * Bn + 255) / 256, 256>>>(beta, out);
}

// round 16
// speedup vs baseline: 1.1810x; 1.0413x over previous
#include <cuda_runtime.h>

#define Bn 2048
#define NB 2000
#define DB 30
#define KK 20
#define LL 40
#define PP 2
#define KSPLIT 8
#define KCH 250         // NB / KSPLIT

typedef unsigned long long u64;

#define LOG2E 1.44269504088896f
#define LN2   0.69314718055995f

// Blob layout (u64 units) per (k,l)
#define OFF_L1 0        // 64:  [p][i] (w*log2e dup, b*log2e dup) as ulonglong2
#define OFF_W2 64       // 512: [p][i][j] dup(W2*log2e)
#define OFF_B2 576      // 32:  [p][i]   dup((b2 - rowsum W2)*log2e)
#define OFF_W3 608      // 256: [p][j][q] dup(W3*log2e)
#define OFF_B3 864      // 16:  [p][j]   dup((b3 - rowsum W3)*log2e)
#define OFF_W4 880      // 16:  [p][j]   dup(W4)
#define OFF_B4 896      // 2:   [p]      dup(b4 - sum W4)
#define OFF_AA 898      // 1:   dup(sigmoid(alpha))
#define BLOBU  904      // padded, 16B-aligned total (7232 B)

// Scratch (no allocations allowed in kernel_launch)
__device__ float d_wact[NB * LL];               // sigmoid(r - kappa)   [NB, L]
__device__ float d_gpart[KSPLIT * LL * Bn];     // split-K partials     [ks, L, B]
__device__ float d_partial[LL * KK * Bn];       // per-(l,k) outputs    [L, K, B]
__device__ __align__(16) u64 d_blob[800 * BLOBU];  // preprocessed weights

// ---------------- packed f32x2 helpers --------------------------------------
__device__ __forceinline__ u64 pack2(float lo, float hi) {
    u64 r; asm("mov.b64 %0, {%1, %2};" : "=l"(r) : "f"(lo), "f"(hi)); return r;
}
__device__ __forceinline__ void unpack2(u64 v, float& lo, float& hi) {
    asm("mov.b64 {%0, %1}, %2;" : "=f"(lo), "=f"(hi) : "l"(v));
}
__device__ __forceinline__ u64 ffma2(u64 a, u64 b, u64 c) {
    u64 d; asm("fma.rn.f32x2 %0, %1, %2, %3;" : "=l"(d) : "l"(a), "l"(b), "l"(c)); return d;
}
__device__ __forceinline__ u64 fadd2(u64 a, u64 b) {
    u64 d; asm("add.rn.f32x2 %0, %1, %2;" : "=l"(d) : "l"(a), "l"(b)); return d;
}
__device__ __forceinline__ u64 fmul2(u64 a, u64 b) {
    u64 d; asm("mul.rn.f32x2 %0, %1, %2;" : "=l"(d) : "l"(a), "l"(b)); return d;
}
__device__ __forceinline__ float ex2(float x) {
    float r; asm("ex2.approx.f32 %0, %1;" : "=f"(r) : "f"(x)); return r;
}
// Clamp-form ELU, packed epilogue: elu(z)+1 = ln2*max(z',0) + exp2(min(z',0)),
// z' = z*log2e. 7 slots per packed pair: 4 FMNMX (alu) + 2 MUFU + 1 FFMA2.
// ln2d = pack2(LN2, LN2) held once per thread; pack/unpack are register renames.
__device__ __forceinline__ u64 elup1v(u64 z, u64 ln2d) {
    float lo, hi; unpack2(z, lo, hi);
    float mnl = fminf(lo, 0.f), mnh = fminf(hi, 0.f);
    float mxl = fmaxf(lo, 0.f), mxh = fmaxf(hi, 0.f);
    u64 e = pack2(ex2(mnl), ex2(mnh));
    return ffma2(pack2(mxl, mxh), ln2d, e);
}

// ---------------------------------------------------------------------------
// Kernel AP (fused): blocks [0, WACT_BLOCKS) compute w_act; the remaining 800
// blocks preprocess weight blobs. The two phases are data-independent.
// ---------------------------------------------------------------------------
#define MT 32
#define DPAD 32
#define WACT_BLOCKS ((NB + MT - 1) / MT)    // 63

__global__ __launch_bounds__(256) void k_wact_prep(
    const float* __restrict__ ml, const float* __restrict__ mu,
    const float* __restrict__ r,
    const float* __restrict__ W1, const float* __restrict__ b1,
    const float* __restrict__ W2, const float* __restrict__ b2,
    const float* __restrict__ W3, const float* __restrict__ b3,
    const float* __restrict__ W4, const float* __restrict__ b4,
    const float* __restrict__ alpha) {
    __shared__ __align__(16) float s_mu[LL * DPAD];
    __shared__ __align__(16) float s_ml[MT * DPAD];
    __shared__ float s_r[LL];
    int tid = threadIdx.x;

    if (blockIdx.x < WACT_BLOCKS) {
        // ---------------- phase A: w_act ----------------
        int m0 = blockIdx.x * MT;
        for (int e = tid; e < LL * DB; e += 256) {
            int l = e / DB, d = e % DB;
            s_mu[l * DPAD + d] = mu[e];
        }
        for (int e = tid; e < MT * DB; e += 256) {
            int mm = e / DB, d = e % DB;
            int m = m0 + mm;
            s_ml[mm * DPAD + d] = (m < NB) ? ml[m * DB + d] : 0.f;
        }
        if (tid < LL) s_r[tid] = r[tid];
        __syncthreads();

        int mm = tid & 31;
        int lg = tid >> 5;
        int m  = m0 + mm;
        if (m >= NB) return;

        float a[DB];
#pragma unroll
        for (int d = 0; d < DB; d++) a[d] = s_ml[mm * DPAD + d];

#pragma unroll
        for (int li = 0; li < 5; li++) {
            int l = lg * 5 + li;
            const float* c = &s_mu[l * DPAD];
            float s = 0.f;
#pragma unroll
            for (int d = 0; d < DB; d++) { float t = a[d] - c[d]; s = fmaf(t, t, s); }
            float z = s_r[l] - s;
            d_wact[m * LL + l] = 1.0f / (1.0f + __expf(-z));
        }
        return;
    }

    // ---------------- phase B: blob prep ----------------
    int kl = blockIdx.x - WACT_BLOCKS;      // 0..799
    int k = kl / LL, l = kl % LL;
    int base = kl * PP;
    u64* blob = d_blob + (size_t)kl * BLOBU;

    if (tid < 32) {
        int p = tid >> 4, i = tid & 15;
        float w = W1[base * 16 + tid] * LOG2E;
        float a = b1[base * 16 + tid] * LOG2E;
        blob[OFF_L1 + (p * 16 + i) * 2]     = pack2(w, w);
        blob[OFF_L1 + (p * 16 + i) * 2 + 1] = pack2(a, a);
        float c = b2[base * 16 + tid];
        const float* w2p = W2 + base * 256 + p * 256;
#pragma unroll
        for (int ii = 0; ii < 16; ii++) c -= w2p[ii * 16 + i];
        c *= LOG2E;
        blob[OFF_B2 + p * 16 + i] = pack2(c, c);
    }
#pragma unroll
    for (int e = tid; e < PP * 256; e += 256) {
        float w = W2[base * 256 + e] * LOG2E;
        blob[OFF_W2 + e] = pack2(w, w);
    }
    if (tid < PP * 128) {
        float w = W3[base * 128 + tid] * LOG2E;
        blob[OFF_W3 + tid] = pack2(w, w);
    }
    if (tid < 16) {
        int p = tid >> 3, j = tid & 7;
        float a = b3[base * 8 + tid];
        const float* w3p = W3 + base * 128 + p * 128;
#pragma unroll
        for (int ii = 0; ii < 16; ii++) a -= w3p[ii * 8 + j];
        a *= LOG2E;
        blob[OFF_B3 + tid] = pack2(a, a);
        float w = W4[base * 8 + tid];
        blob[OFF_W4 + tid] = pack2(w, w);
    }
    if (tid < 2) {
        float a = b4[base + tid];
        const float* w4p = W4 + base * 8 + tid * 8;
#pragma unroll
        for (int ii = 0; ii < 8; ii++) a -= w4p[ii];
        blob[OFF_B4 + tid] = pack2(a, a);
    }
    if (tid == 0) {
        float aAct = 1.0f / (1.0f + __expf(-alpha[l * KK + k]));
        blob[OFF_AA] = pack2(aAct, aAct);
    }
}

// ---------------------------------------------------------------------------
// Kernel B: split-K GEMM (KSPLIT=8). gpart[ks,l,b] = sum_slice x[b,m]*wact[m,l]
// ---------------------------------------------------------------------------
#define CH 128
#define XS 132
#define WS 132

__global__ __launch_bounds__(320) void k_gemm(const float* __restrict__ x) {
    __shared__ __align__(16) float xs[16 * XS];
    __shared__ __align__(16) float ws[LL * WS];     // [l][mm]
    int b0   = blockIdx.x * 16;
    int ks   = blockIdx.y;
    int mlo  = ks * KCH;
    int mend = mlo + KCH;
    int tid = threadIdx.x;
    int row = tid & 15;
    int cg  = tid >> 4;
    u64 acc0 = 0ull, acc1 = 0ull;
    for (int m0 = mlo; m0 < mend; m0 += CH) {
        for (int e = tid; e < 16 * CH; e += 320) {
            int rr = e >> 7, cc = e & (CH - 1);
            int m = m0 + cc;
            xs[rr * XS + cc] = (m < mend) ? x[(b0 + rr) * NB + m] : 0.f;
        }
        for (int e = tid; e < CH * LL; e += 320) {
            int mm = e / LL, l = e % LL;
            int m = m0 + mm;
            ws[l * WS + mm] = (m < mend) ? d_wact[m * LL + l] : 0.f;
        }
        __syncthreads();
#pragma unroll 4
        for (int mm = 0; mm < CH; mm += 4) {
            float4 xv = *(const float4*)&xs[row * XS + mm];
            float4 w0 = *(const float4*)&ws[(2 * cg)     * WS + mm];
            float4 w1 = *(const float4*)&ws[(2 * cg + 1) * WS + mm];
            u64 xa = pack2(xv.x, xv.y), xb = pack2(xv.z, xv.w);
            acc0 = ffma2(xa, pack2(w0.x, w0.y), acc0);
            acc0 = ffma2(xb, pack2(w0.z, w0.w), acc0);
            acc1 = ffma2(xa, pack2(w1.x, w1.y), acc1);
            acc1 = ffma2(xb, pack2(w1.z, w1.w), acc1);
        }
        __syncthreads();
    }
    float a0l, a0h, a1l, a1h;
    unpack2(acc0, a0l, a0h);
    unpack2(acc1, a1l, a1h);
    float* gp = d_gpart + ks * (LL * Bn);
    gp[(2 * cg)     * Bn + b0 + row] = a0l + a0h;
    gp[(2 * cg + 1) * Bn + b0 + row] = a1l + a1h;
}

// ---------------------------------------------------------------------------
// Kernel C: NAM. 6400 light blocks, 64 threads, 8 blocks/SM. 7-slot packed
// clamp ELU. g reconstructed from 8 split-K partials inline.
// ---------------------------------------------------------------------------
__global__ __launch_bounds__(64, 8) void k_nam() {
    __shared__ __align__(16) u64 sm[BLOBU];
    int unit = blockIdx.x;
    int kl = unit >> 3, e8 = unit & 7;
    int tid = threadIdx.x;

    const u64* blob = d_blob + (size_t)kl * BLOBU;
#pragma unroll
    for (int e = tid; e < BLOBU / 2; e += 64)
        ((ulonglong2*)sm)[e] = ((const ulonglong2*)blob)[e];
    __syncthreads();

    int k = kl / LL, l = kl % LL;
    u64 aAct2 = sm[OFF_AA];
    u64 ln2d = pack2(LN2, LN2);
    float* outp = d_partial + (l * KK + k) * Bn + e8 * 256;
    const float* gp = d_gpart + l * Bn + e8 * 256;

    int b0 = 2 * tid;                       // pairA at b0, pairB at b0+128
    u64 GA = 0ull, GB = 0ull;
#pragma unroll
    for (int ks = 0; ks < KSPLIT; ks++) {
        float2 va = *(const float2*)&gp[ks * (LL * Bn) + b0];
        float2 vb = *(const float2*)&gp[ks * (LL * Bn) + b0 + 128];
        GA = fadd2(GA, pack2(va.x, va.y));
        GB = fadd2(GB, pack2(vb.x, vb.y));
    }
    u64 SA = 0ull, SB = 0ull;

#pragma unroll 1
    for (int p = 0; p < PP; p++) {
        // ---- layer 1 streamed into layer-2 accumulators ----
        u64 a2[16][2];
#pragma unroll
        for (int j = 0; j < 16; j++) {
            u64 bb = sm[OFF_B2 + p * 16 + j];
            a2[j][0] = bb; a2[j][1] = bb;
        }
#pragma unroll
        for (int i = 0; i < 16; i++) {
            ulonglong2 wb = ((const ulonglong2*)(sm + OFF_L1))[p * 16 + i];
            u64 hA = elup1v(ffma2(GA, wb.x, wb.y), ln2d);
            u64 hB = elup1v(ffma2(GB, wb.x, wb.y), ln2d);
            const ulonglong2* wr = (const ulonglong2*)(sm + OFF_W2 + p * 256 + i * 16);
#pragma unroll
            for (int q = 0; q < 8; q++) {
                ulonglong2 w = wr[q];
                a2[2 * q][0]     = ffma2(hA, w.x, a2[2 * q][0]);
                a2[2 * q + 1][0] = ffma2(hA, w.y, a2[2 * q + 1][0]);
                a2[2 * q][1]     = ffma2(hB, w.x, a2[2 * q][1]);
                a2[2 * q + 1][1] = ffma2(hB, w.y, a2[2 * q + 1][1]);
            }
        }

        // ---- layer 2 -> layer 3 accumulators ----
        u64 a3[8][2];
#pragma unroll
        for (int q = 0; q < 8; q++) {
            u64 bb = sm[OFF_B3 + p * 8 + q];
            a3[q][0] = bb; a3[q][1] = bb;
        }
#pragma unroll
        for (int j = 0; j < 16; j++) {
            u64 vA = elup1v(a2[j][0], ln2d);
            u64 vB = elup1v(a2[j][1], ln2d);
            const ulonglong2* wr = (const ulonglong2*)(sm + OFF_W3 + p * 128 + j * 8);
#pragma unroll
            for (int q = 0; q < 4; q++) {
                ulonglong2 w = wr[q];
                a3[2 * q][0]     = ffma2(vA, w.x, a3[2 * q][0]);
                a3[2 * q + 1][0] = ffma2(vA, w.y, a3[2 * q + 1][0]);
                a3[2 * q][1]     = ffma2(vB, w.x, a3[2 * q][1]);
                a3[2 * q + 1][1] = ffma2(vB, w.y, a3[2 * q + 1][1]);
            }
        }

        // ---- layer 3 -> scalar ----
        u64 fA = sm[OFF_B4 + p], fB = fA;
#pragma unroll
        for (int j = 0; j < 8; j++) {
            u64 vA = elup1v(a3[j][0], ln2d);
            u64 vB = elup1v(a3[j][1], ln2d);
            u64 w = sm[OFF_W4 + p * 8 + j];
            fA = ffma2(vA, w, fA);
            fB = ffma2(vB, w, fB);
        }
        SA = fadd2(SA, fA);
        SB = fadd2(SB, fB);
    }

    u64 r0 = fmul2(aAct2, SA);
    u64 r1 = fmul2(aAct2, SB);
    float lo, hi;
    unpack2(r0, lo, hi); *(float2*)&outp[b0]       = make_float2(lo, hi);
    unpack2(r1, lo, hi); *(float2*)&outp[b0 + 128] = make_float2(lo, hi);
}

// ---------------------------------------------------------------------------
// Kernel D: out[b,k] = beta[k] + sum_l partial[l,k,b]  (scalar, high-occ)
// ---------------------------------------------------------------------------
__global__ void k_out(const float* __restrict__ beta, float* __restrict__ out) {
    int idx = blockIdx.x * blockDim.x + threadIdx.x;
    if (idx >= KK * Bn) return;
    int k = idx >> 11;
    int b = idx & (Bn - 1);
    float s = beta[k];
#pragma unroll
    for (int l = 0; l < LL; l++) s += d_partial[(l * KK + k) * Bn + b];
    out[b * KK + k] = s;
}

// ---------------------------------------------------------------------------
extern "C" void kernel_launch(void* const* d_in, const int* in_sizes, int n_in,
                              void* d_out, int out_size) {
    const float* x     = (const float*)d_in[0];
    const float* ml    = (const float*)d_in[1];
    const float* mu    = (const float*)d_in[2];
    const float* r     = (const float*)d_in[3];
    const float* alpha = (const float*)d_in[4];
    const float* beta  = (const float*)d_in[5];
    const float* W1    = (const float*)d_in[6];
    const float* b1    = (const float*)d_in[7];
    const float* W2    = (const float*)d_in[8];
    const float* b2    = (const float*)d_in[9];
    const float* W3    = (const float*)d_in[10];
    const float* b3    = (const float*)d_in[11];
    const float* W4    = (const float*)d_in[12];
    const float* b4    = (const float*)d_in[13];
    float* out = (float*)d_out;

    k_wact_prep<<<WACT_BLOCKS + KK * LL, 256>>>(ml, mu, r,
        W1, b1, W2, b2, W3, b3, W4, b4, alpha);
    dim3 ggrid(Bn / 16, KSPLIT);
    k_gemm<<<ggrid, 320>>>(x);
    k_nam<<<KK * LL * 8, 64>>>();
    k_out<<<(KK * Bn + 255) / 256, 256>>>(beta, out);
}